// round 11
// baseline (speedup 1.0000x reference)
#include <cuda_runtime.h>
#include <math.h>

#define Bsz 8
#define Tt  16
#define NCc 128

typedef unsigned long long u64;

// bf16-packed MLP weights:
//   g_w1p[d*64 + c2]  = bf16(w1T[d][2c2])   | bf16(w1T[d][2c2+1])<<16   (column-pair)
//   g_w2p[h2*64 + c]  = bf16(w2T[2h2][c])   | bf16(w2T[2h2+1][c])<<16   (h-pair)
__device__ __align__(16) unsigned g_w1p[64 * 64];
__device__ __align__(16) unsigned g_w2p[64 * 64];
__device__ __align__(16) float g_inj[Bsz * Tt * NCc * 256];

__device__ __forceinline__ unsigned bfr(float f) {   // f32 -> bf16 bits (rn)
    unsigned u = __float_as_uint(f);
    return (u + 0x7FFFu + ((u >> 16) & 1u)) >> 16;
}

// Prep: pack weights + precompute inj[b,t,c,k]. grid=128, block=256.
__global__ __launch_bounds__(256) void mg_prep(const float* __restrict__ x,
                                               const float* __restrict__ injw,
                                               const float* __restrict__ injb,
                                               const float* __restrict__ w1,
                                               const float* __restrict__ w2) {
    const int c = blockIdx.x, k = threadIdx.x;
    const int idx = c * 256 + k;
    if (idx < 4096) {
        const int d = idx >> 6, c2 = idx & 63;            // w1 is [128][64]
        g_w1p[idx] = bfr(w1[(2 * c2) * 64 + d]) | (bfr(w1[(2 * c2 + 1) * 64 + d]) << 16);
        const int h2 = idx >> 6, cc = idx & 63;           // w2 is [64][128]
        g_w2p[idx] = bfr(w2[cc * 128 + 2 * h2]) | (bfr(w2[cc * 128 + 2 * h2 + 1]) << 16);
    }
    __shared__ float sx[64];
    float4 wv[16];
    const float4* wrow = reinterpret_cast<const float4*>(injw + (long)(c * 256 + k) * 64);
    #pragma unroll
    for (int q = 0; q < 16; q++) wv[q] = __ldg(wrow + q);
    const float bias = injb[c * 256 + k];
    for (int bt = 0; bt < Bsz * Tt; bt++) {
        if (k < 64) sx[k] = x[((long)bt * NCc + c) * 64 + k];
        __syncthreads();
        float acc = bias;
        #pragma unroll
        for (int q = 0; q < 16; q++) {
            float4 xv = *reinterpret_cast<const float4*>(sx + 4 * q);
            acc = fmaf(wv[q].x, xv.x, acc); acc = fmaf(wv[q].y, xv.y, acc);
            acc = fmaf(wv[q].z, xv.z, acc); acc = fmaf(wv[q].w, xv.w, acc);
        }
        g_inj[((long)bt * NCc + c) * 256 + k] = acc;
        __syncthreads();
    }
}

__device__ __forceinline__ u64 dup2(float a) {
    u64 r; asm("mov.b64 %0, {%1, %1};" : "=l"(r) : "r"(__float_as_uint(a))); return r;
}
__device__ __forceinline__ u64 fma2(u64 a, u64 b, u64 c) {
    u64 d; asm("fma.rn.f32x2 %0, %1, %2, %3;" : "=l"(d) : "l"(a), "l"(b), "l"(c)); return d;
}
__device__ __forceinline__ void up2(u64 v, float& a, float& b) {
    unsigned x, y; asm("mov.b64 {%0, %1}, %2;" : "=r"(x), "=r"(y) : "l"(v));
    a = __uint_as_float(x); b = __uint_as_float(y);
}
__device__ __forceinline__ u64 pku(unsigned a, unsigned b) {
    u64 d; asm("mov.b64 %0, {%1, %2};" : "=l"(d) : "r"(a), "r"(b)); return d;
}
__device__ __forceinline__ u64 bfp(unsigned r) {            // col-pair -> f32x2
    return pku(r << 16, r & 0xFFFF0000u);
}
__device__ __forceinline__ u64 blo(unsigned x, unsigned y) { return pku(x << 16, y << 16); }
__device__ __forceinline__ u64 bhi(unsigned x, unsigned y) { return pku(x & 0xFFFF0000u, y & 0xFFFF0000u); }
// exact-formula fast tanh: 1 - 2/(2^(2x*log2e)+1)  (ex2+rcp MUFU, abs err ~1e-7)
__device__ __forceinline__ float tfast(float x) {
    float e, r;
    asm("ex2.approx.f32 %0, %1;" : "=f"(e) : "f"(x * 2.8853900817779268f));
    asm("rcp.approx.f32 %0, %1;" : "=f"(r) : "f"(e + 1.0f));
    return fmaf(-2.0f, r, 1.0f);
}

// XOR chunk swizzle (16B chunks permuted per row)
__device__ __forceinline__ int pr(int r)           { return (r ^ (r >> 3)) & 7; }
__device__ __forceinline__ int a64(int r, int cq)  { return (r << 6) + ((cq ^ pr(r)) << 2); }
__device__ __forceinline__ int a64s(int r, int c)  { return (r << 6) + (((c >> 2) ^ pr(r)) << 2) + (c & 3); }
__device__ __forceinline__ int a128(int r, int cq) { return (r << 7) + ((cq ^ pr(r)) << 2); }

__global__ __launch_bounds__(256, 2)
void mg_main(const float* __restrict__ h0,    const float* __restrict__ W0,
             const float* __restrict__ heb0,  const float* __restrict__ nid,
             const float* __restrict__ wdl,   const float* __restrict__ dgl,
             const float* __restrict__ hdl,   const float* __restrict__ b1g,
             const float* __restrict__ b2g,
             const int*   __restrict__ ipi,   const int*   __restrict__ opi,
             float* __restrict__ out) {
    extern __shared__ float sm[];
    float* sH    = sm;               // 4096 (a64 swizzled)
    float* sW0   = sH    + 4096;
    float* sHeb  = sW0   + 4096;
    float* sM    = sHeb  + 4096;
    float* sBuf  = sM    + 4096;     // 8192: Wh (a64) then hidden (a128)
    float* sGam  = sBuf  + 8192;     // 64
    float* sHg   = sGam  + 64;
    float* sOmWg = sHg   + 64;
    float* sDecW = sOmWg + 64;
    float* sB1   = sDecW + 64;       // 128
    float* sB2   = sB1   + 128;      // 64
    __shared__ int sIp[4], sOp[4];

    const int tid = threadIdx.x;
    const int c   = blockIdx.x / Bsz;
    const int b   = blockIdx.x % Bsz;
    const long base = (long)(b * NCc + c) * 4096;

    if (tid < 64) {
        sGam[tid]  = 0.5f / (1.0f + expf(-dgl[c * 64 + tid]));
        sHg[tid]   = 0.5f / (1.0f + expf(-hdl[c * 64 + tid]));
        sOmWg[tid] = 1.0f - 0.5f / (1.0f + expf(-wdl[c * 64 + tid]));
        sDecW[tid] = 1.0f;
        sB2[tid]   = b2g[tid];
    }
    if (tid < 128) sB1[tid] = b1g[tid];
    if (tid < 4) { sIp[tid] = ipi[c * 4 + tid]; sOp[tid] = opi[c * 4 + tid]; }
    for (int k = tid; k < 1024; k += 256) {       // swizzled fill
        const int r = k >> 4, cq = k & 15, so = a64(r, cq);
        const long go = base + ((long)k << 2);
        *reinterpret_cast<float4*>(sH   + so) = __ldg(reinterpret_cast<const float4*>(h0   + go));
        *reinterpret_cast<float4*>(sW0  + so) = __ldg(reinterpret_cast<const float4*>(W0   + go));
        *reinterpret_cast<float4*>(sHeb + so) = __ldg(reinterpret_cast<const float4*>(heb0 + go));
    }
    __syncthreads();

    // P0 (t=0): Wh = W0 + heb; scatter inj(t=0)
    for (int k = tid; k < 1024; k += 256) {
        const int o = k << 2;
        float4 w = *reinterpret_cast<const float4*>(sW0 + o);
        float4 hb = *reinterpret_cast<const float4*>(sHeb + o);
        *reinterpret_cast<float4*>(sBuf + o) = make_float4(w.x + hb.x, w.y + hb.y, w.z + hb.z, w.w + hb.w);
    }
    if (tid < 64) {
        const long ib = ((long)(b * Tt) * NCc + c) * 256 + tid;
        #pragma unroll
        for (int a = 0; a < 4; a++)
            sH[a64s(sIp[a], tid)] += __ldg(g_inj + ib + a * 64);
    }
    __syncthreads();

    // warp-block mapping
    const int wid = tid >> 5, lane = tid & 31;
    const int lr = lane >> 2, lc = lane & 3;
    const int r0   = (wid & 1) * 32 + lr * 4;
    const int cb   = (wid >> 1) * 16;
    const int c0   = cb + lc * 4;
    const int cq0  = c0 >> 2;
    const int p3c0 = (wid >> 1) * 32 + lc * 8;
    const int p3cq = p3c0 >> 2;
    const int pc2  = p3c0 >> 1;          // w1p column-pair base

    for (int t = 0; t < Tt; ++t) {
        // ===== P2: m = Wh @ h_in (4x4 tiles) =====
        {
            u64 acc[4][2];
            #pragma unroll
            for (int ii = 0; ii < 4; ii++) { acc[ii][0] = acc[ii][1] = 0ULL; }
            #pragma unroll 4
            for (int j = 0; j < 64; j += 4) {
                float4 wr[4]; ulonglong2 hv[4];
                #pragma unroll
                for (int ii = 0; ii < 4; ii++)
                    wr[ii] = *reinterpret_cast<const float4*>(sBuf + a64(r0 + ii, j >> 2));
                #pragma unroll
                for (int jj = 0; jj < 4; jj++)
                    hv[jj] = *reinterpret_cast<const ulonglong2*>(sH + a64(j + jj, cq0));
                #pragma unroll
                for (int ii = 0; ii < 4; ii++) {
                    const float* wf = reinterpret_cast<const float*>(&wr[ii]);
                    #pragma unroll
                    for (int jj = 0; jj < 4; jj++) {
                        u64 wd = dup2(wf[jj]);
                        acc[ii][0] = fma2(wd, hv[jj].x, acc[ii][0]);
                        acc[ii][1] = fma2(wd, hv[jj].y, acc[ii][1]);
                    }
                }
            }
            #pragma unroll
            for (int ii = 0; ii < 4; ii++) {
                ulonglong2 v; v.x = acc[ii][0]; v.y = acc[ii][1];
                *reinterpret_cast<ulonglong2*>(sM + a64(r0 + ii, cq0)) = v;
            }
        }
        __syncthreads();

        // ===== P3: hidden = tanh(m @ w1T + b1), bf16-packed weights =====
        {
            u64 acc[4][4];
            #pragma unroll
            for (int ii = 0; ii < 4; ii++) { acc[ii][0]=acc[ii][1]=acc[ii][2]=acc[ii][3]=0ULL; }
            #pragma unroll 4
            for (int kk = 0; kk < 16; kk++) {           // 4 d per iter
                const int d0 = kk * 4;
                uint4 wq[4];
                #pragma unroll
                for (int dd = 0; dd < 4; dd++)
                    wq[dd] = __ldg(reinterpret_cast<const uint4*>(g_w1p + (d0 + dd) * 64 + pc2));
                float4 mv[4];
                #pragma unroll
                for (int ii = 0; ii < 4; ii++)
                    mv[ii] = *reinterpret_cast<const float4*>(sM + a64(r0 + ii, kk));
                #pragma unroll
                for (int dd = 0; dd < 4; dd++) {
                    const u64 W0p = bfp(wq[dd].x), W1p = bfp(wq[dd].y);
                    const u64 W2p = bfp(wq[dd].z), W3p = bfp(wq[dd].w);
                    #pragma unroll
                    for (int ii = 0; ii < 4; ii++) {
                        const float mval = reinterpret_cast<const float*>(&mv[ii])[dd];
                        const u64 md = dup2(mval);
                        acc[ii][0] = fma2(md, W0p, acc[ii][0]);
                        acc[ii][1] = fma2(md, W1p, acc[ii][1]);
                        acc[ii][2] = fma2(md, W2p, acc[ii][2]);
                        acc[ii][3] = fma2(md, W3p, acc[ii][3]);
                    }
                }
            }
            #pragma unroll
            for (int ii = 0; ii < 4; ii++) {
                const int r = r0 + ii;
                float v[8];
                up2(acc[ii][0], v[0], v[1]); up2(acc[ii][1], v[2], v[3]);
                up2(acc[ii][2], v[4], v[5]); up2(acc[ii][3], v[6], v[7]);
                float4 o0, o1;
                o0.x = tfast(v[0] + sB1[p3c0 + 0]); o0.y = tfast(v[1] + sB1[p3c0 + 1]);
                o0.z = tfast(v[2] + sB1[p3c0 + 2]); o0.w = tfast(v[3] + sB1[p3c0 + 3]);
                o1.x = tfast(v[4] + sB1[p3c0 + 4]); o1.y = tfast(v[5] + sB1[p3c0 + 5]);
                o1.z = tfast(v[6] + sB1[p3c0 + 6]); o1.w = tfast(v[7] + sB1[p3c0 + 7]);
                *reinterpret_cast<float4*>(sBuf + a128(r, p3cq))     = o0;
                *reinterpret_cast<float4*>(sBuf + a128(r, p3cq + 1)) = o1;
            }
        }
        __syncthreads();

        // ===== P4: MLP2 + gated update, bf16 h-pair weights =====
        {
            u64 acc[4][2];
            #pragma unroll
            for (int ii = 0; ii < 4; ii++) { acc[ii][0] = acc[ii][1] = 0ULL; }
            #pragma unroll 4
            for (int kk = 0; kk < 32; kk++) {           // 4 h per iter (2 h-pairs)
                uint4 wq[2];
                #pragma unroll
                for (int j = 0; j < 2; j++)
                    wq[j] = __ldg(reinterpret_cast<const uint4*>(g_w2p + (kk * 2 + j) * 64 + c0));
                float4 tv[4];
                #pragma unroll
                for (int ii = 0; ii < 4; ii++)
                    tv[ii] = *reinterpret_cast<const float4*>(sBuf + a128(r0 + ii, kk));
                #pragma unroll
                for (int j = 0; j < 2; j++) {
                    const u64 La = blo(wq[j].x, wq[j].y), Lb = blo(wq[j].z, wq[j].w);
                    const u64 Ha = bhi(wq[j].x, wq[j].y), Hb = bhi(wq[j].z, wq[j].w);
                    #pragma unroll
                    for (int ii = 0; ii < 4; ii++) {
                        const float* tf = reinterpret_cast<const float*>(&tv[ii]);
                        const u64 te = dup2(tf[2 * j]), to = dup2(tf[2 * j + 1]);
                        acc[ii][0] = fma2(te, La, acc[ii][0]);
                        acc[ii][1] = fma2(te, Lb, acc[ii][1]);
                        acc[ii][0] = fma2(to, Ha, acc[ii][0]);
                        acc[ii][1] = fma2(to, Hb, acc[ii][1]);
                    }
                }
            }
            #pragma unroll
            for (int ii = 0; ii < 4; ii++) {
                const int i = r0 + ii, o = a64(i, cq0);
                const float g = sGam[i], omg = 1.0f - g;
                float4 nv = __ldg(reinterpret_cast<const float4*>(nid + ((long)c * 64 + i) * 64 + c0));
                float v[4];
                up2(acc[ii][0], v[0], v[1]); up2(acc[ii][1], v[2], v[3]);
                float4 hc = *reinterpret_cast<const float4*>(sH + o);
                float4 ov;
                ov.x = omg * hc.x + g * tfast(v[0] + sB2[c0 + 0] + nv.x);
                ov.y = omg * hc.y + g * tfast(v[1] + sB2[c0 + 1] + nv.y);
                ov.z = omg * hc.z + g * tfast(v[2] + sB2[c0 + 2] + nv.z);
                ov.w = omg * hc.w + g * tfast(v[3] + sB2[c0 + 3] + nv.w);
                *reinterpret_cast<float4*>(sH + o) = ov;
            }
        }
        __syncthreads();

        // ===== P5a: readout + gram + decay =====
        if (tid < 64) {
            float s = sH[a64s(sOp[0], tid)] + sH[a64s(sOp[1], tid)]
                    + sH[a64s(sOp[2], tid)] + sH[a64s(sOp[3], tid)];
            out[((long)(b * Tt + t) * NCc + c) * 64 + tid] = s * 0.125f;
            sDecW[tid] *= sOmWg[tid];
        }
        u64 acc5[4][4];
        {
            #pragma unroll
            for (int ii = 0; ii < 4; ii++) { acc5[ii][0]=acc5[ii][1]=acc5[ii][2]=acc5[ii][3]=0ULL; }
            #pragma unroll 4
            for (int dq = 0; dq < 64; dq += 4) {
                ulonglong2 hi[4], hj[4];
                #pragma unroll
                for (int ii = 0; ii < 4; ii++)
                    hi[ii] = *reinterpret_cast<const ulonglong2*>(sH + a64(r0 + ii, dq >> 2));
                #pragma unroll
                for (int jj = 0; jj < 4; jj++)
                    hj[jj] = *reinterpret_cast<const ulonglong2*>(sH + a64(c0 + jj, dq >> 2));
                #pragma unroll
                for (int ii = 0; ii < 4; ii++)
                    #pragma unroll
                    for (int jj = 0; jj < 4; jj++) {
                        acc5[ii][jj] = fma2(hi[ii].x, hj[jj].x, acc5[ii][jj]);
                        acc5[ii][jj] = fma2(hi[ii].y, hj[jj].y, acc5[ii][jj]);
                    }
            }
        }
        __syncthreads();

        // ===== P5b: heb store + next Wh build + scatter inj(t+1) =====
        {
            const bool more = (t + 1 < Tt);
            #pragma unroll
            for (int ii = 0; ii < 4; ii++) {
                const int i = r0 + ii, o = a64(i, cq0);
                const float hgv = sHg[i], omh = 1.0f - hgv, sc = hgv * (1.0f / 64.0f);
                float4 e = *reinterpret_cast<const float4*>(sHeb + o);
                float v[4];
                #pragma unroll
                for (int jj = 0; jj < 4; jj++) { float pa, pb; up2(acc5[ii][jj], pa, pb); v[jj] = pa + pb; }
                v[0] = omh * e.x + sc * v[0]; v[1] = omh * e.y + sc * v[1];
                v[2] = omh * e.z + sc * v[2]; v[3] = omh * e.w + sc * v[3];
                #pragma unroll
                for (int jj = 0; jj < 4; jj++) if (i == c0 + jj) v[jj] = 0.0f;
                float4 hn = make_float4(v[0], v[1], v[2], v[3]);
                *reinterpret_cast<float4*>(sHeb + o) = hn;
                if (more) {
                    const float pwn = sDecW[i];
                    float4 w = *reinterpret_cast<const float4*>(sW0 + o);
                    float4 wh;
                    wh.x = fmaf(pwn, w.x, hn.x); wh.y = fmaf(pwn, w.y, hn.y);
                    wh.z = fmaf(pwn, w.z, hn.z); wh.w = fmaf(pwn, w.w, hn.w);
                    *reinterpret_cast<float4*>(sBuf + o) = wh;
                }
            }
            if (more && tid < 64) {
                const long ib = ((long)(b * Tt + t + 1) * NCc + c) * 256 + tid;
                #pragma unroll
                for (int a = 0; a < 4; a++)
                    sH[a64s(sIp[a], tid)] += __ldg(g_inj + ib + a * 64);
            }
        }
        __syncthreads();
    }
}

extern "C" void kernel_launch(void* const* d_in, const int* in_sizes, int n_in,
                              void* d_out, int out_size) {
    const float* x    = (const float*)d_in[0];
    const float* h0   = (const float*)d_in[1];
    const float* W0   = (const float*)d_in[2];
    const float* heb0 = (const float*)d_in[3];
    const float* nid  = (const float*)d_in[4];
    const float* w1   = (const float*)d_in[5];
    const float* b1   = (const float*)d_in[6];
    const float* w2   = (const float*)d_in[7];
    const float* b2   = (const float*)d_in[8];
    const float* injw = (const float*)d_in[9];
    const float* injb = (const float*)d_in[10];
    const float* wdl  = (const float*)d_in[11];
    const float* dgl  = (const float*)d_in[12];
    const float* hdl  = (const float*)d_in[13];
    const int*   ipi  = (const int*)d_in[14];
    const int*   opi  = (const int*)d_in[15];
    float* out = (float*)d_out;

    const int smem_bytes = (4096 * 4 + 8192 + 64 * 4 + 128 + 64) * 4;
    cudaFuncSetAttribute(mg_main, cudaFuncAttributeMaxDynamicSharedMemorySize, smem_bytes);

    mg_prep<<<NCc, 256>>>(x, injw, injb, w1, w2);
    mg_main<<<NCc * Bsz, 256, smem_bytes>>>(h0, W0, heb0, nid, wdl, dgl, hdl,
                                            b1, b2, ipi, opi, out);
}

// round 12
// speedup vs baseline: 1.0497x; 1.0497x over previous
#include <cuda_runtime.h>
#include <math.h>

#define Bsz 8
#define Tt  16
#define NCc 128

typedef unsigned long long u64;

__device__ __align__(16) float g_w1T[64 * 128];
__device__ __align__(16) float g_w2T[128 * 64];
__device__ __align__(16) float g_inj[Bsz * Tt * NCc * 256];

// Prep: transpose MLP weights + precompute inj[b,t,c,k]. grid=128, block=256.
__global__ __launch_bounds__(256) void mg_prep(const float* __restrict__ x,
                                               const float* __restrict__ injw,
                                               const float* __restrict__ injb,
                                               const float* __restrict__ w1,
                                               const float* __restrict__ w2) {
    const int c = blockIdx.x, k = threadIdx.x;
    const int idx = c * 256 + k;
    if (idx < 8192) {
        int h = idx / 64, d = idx % 64;
        g_w1T[d * 128 + h] = w1[idx];
        int d2 = idx / 128, h2 = idx % 128;
        g_w2T[h2 * 64 + d2] = w2[idx];
    }
    __shared__ float sx[64];
    float4 wv[16];
    const float4* wrow = reinterpret_cast<const float4*>(injw + (long)(c * 256 + k) * 64);
    #pragma unroll
    for (int q = 0; q < 16; q++) wv[q] = __ldg(wrow + q);
    const float bias = injb[c * 256 + k];
    for (int bt = 0; bt < Bsz * Tt; bt++) {
        if (k < 64) sx[k] = x[((long)bt * NCc + c) * 64 + k];
        __syncthreads();
        float acc = bias;
        #pragma unroll
        for (int q = 0; q < 16; q++) {
            float4 xv = *reinterpret_cast<const float4*>(sx + 4 * q);
            acc = fmaf(wv[q].x, xv.x, acc); acc = fmaf(wv[q].y, xv.y, acc);
            acc = fmaf(wv[q].z, xv.z, acc); acc = fmaf(wv[q].w, xv.w, acc);
        }
        g_inj[((long)bt * NCc + c) * 256 + k] = acc;
        __syncthreads();
    }
}

__device__ __forceinline__ u64 dup2(float a) {
    u64 r; asm("mov.b64 %0, {%1, %1};" : "=l"(r) : "r"(__float_as_uint(a))); return r;
}
__device__ __forceinline__ u64 fma2(u64 a, u64 b, u64 c) {
    u64 d; asm("fma.rn.f32x2 %0, %1, %2, %3;" : "=l"(d) : "l"(a), "l"(b), "l"(c)); return d;
}
__device__ __forceinline__ void up2(u64 v, float& a, float& b) {
    unsigned x, y; asm("mov.b64 {%0, %1}, %2;" : "=r"(x), "=r"(y) : "l"(v));
    a = __uint_as_float(x); b = __uint_as_float(y);
}
// exact-formula fast tanh: 1 - 2/(2^(2x*log2e)+1)  (ex2+rcp MUFU, abs err ~1e-7)
__device__ __forceinline__ float tfast(float x) {
    float e, r;
    asm("ex2.approx.f32 %0, %1;" : "=f"(e) : "f"(x * 2.8853900817779268f));
    asm("rcp.approx.f32 %0, %1;" : "=f"(r) : "f"(e + 1.0f));
    return fmaf(-2.0f, r, 1.0f);
}

// XOR chunk swizzle (16B chunks permuted per row)
__device__ __forceinline__ int pr(int r)           { return (r ^ (r >> 3)) & 7; }
__device__ __forceinline__ int a64(int r, int cq)  { return (r << 6) + ((cq ^ pr(r)) << 2); }
__device__ __forceinline__ int a64s(int r, int c)  { return (r << 6) + (((c >> 2) ^ pr(r)) << 2) + (c & 3); }
__device__ __forceinline__ int a128(int r, int cq) { return (r << 7) + ((cq ^ pr(r)) << 2); }

__global__ __launch_bounds__(256, 2)
void mg_main(const float* __restrict__ h0,    const float* __restrict__ W0,
             const float* __restrict__ heb0,  const float* __restrict__ nid,
             const float* __restrict__ wdl,   const float* __restrict__ dgl,
             const float* __restrict__ hdl,   const float* __restrict__ b1g,
             const float* __restrict__ b2g,
             const int*   __restrict__ ipi,   const int*   __restrict__ opi,
             float* __restrict__ out) {
    extern __shared__ float sm[];
    float* sH    = sm;               // 4096 (a64 swizzled)
    float* sW0   = sH    + 4096;
    float* sHeb  = sW0   + 4096;
    float* sM    = sHeb  + 4096;
    float* sBuf  = sM    + 4096;     // 8192: Wh (a64) then hidden (a128)
    float* sGam  = sBuf  + 8192;     // 64
    float* sHg   = sGam  + 64;
    float* sOmWg = sHg   + 64;
    float* sDecW = sOmWg + 64;
    float* sB1   = sDecW + 64;       // 128
    float* sB2   = sB1   + 128;      // 64
    __shared__ int sIp[4], sOp[4];

    const int tid = threadIdx.x;
    const int c   = blockIdx.x / Bsz;
    const int b   = blockIdx.x % Bsz;
    const long base = (long)(b * NCc + c) * 4096;

    if (tid < 64) {
        sGam[tid]  = 0.5f / (1.0f + expf(-dgl[c * 64 + tid]));
        sHg[tid]   = 0.5f / (1.0f + expf(-hdl[c * 64 + tid]));
        sOmWg[tid] = 1.0f - 0.5f / (1.0f + expf(-wdl[c * 64 + tid]));
        sDecW[tid] = 1.0f;
        sB2[tid]   = b2g[tid];
    }
    if (tid < 128) sB1[tid] = b1g[tid];
    if (tid < 4) { sIp[tid] = ipi[c * 4 + tid]; sOp[tid] = opi[c * 4 + tid]; }
    for (int k = tid; k < 1024; k += 256) {       // swizzled fill
        const int r = k >> 4, cq = k & 15, so = a64(r, cq);
        const long go = base + ((long)k << 2);
        *reinterpret_cast<float4*>(sH   + so) = __ldg(reinterpret_cast<const float4*>(h0   + go));
        *reinterpret_cast<float4*>(sW0  + so) = __ldg(reinterpret_cast<const float4*>(W0   + go));
        *reinterpret_cast<float4*>(sHeb + so) = __ldg(reinterpret_cast<const float4*>(heb0 + go));
    }
    __syncthreads();

    // ===== P0 (t=0 only): Wh = W0 + heb; scatter inj(t=0) =====
    for (int k = tid; k < 1024; k += 256) {
        const int o = k << 2;
        float4 w = *reinterpret_cast<const float4*>(sW0 + o);
        float4 hb = *reinterpret_cast<const float4*>(sHeb + o);
        *reinterpret_cast<float4*>(sBuf + o) = make_float4(w.x + hb.x, w.y + hb.y, w.z + hb.z, w.w + hb.w);
    }
    if (tid < 64) {
        const long ib = ((long)(b * Tt) * NCc + c) * 256 + tid;
        #pragma unroll
        for (int a = 0; a < 4; a++)
            sH[a64s(sIp[a], tid)] += __ldg(g_inj + ib + a * 64);
    }
    __syncthreads();

    // warp-block mapping
    const int wid = tid >> 5, lane = tid & 31;
    const int lr = lane >> 2, lc = lane & 3;
    const int r0   = (wid & 1) * 32 + lr * 4;
    const int cb   = (wid >> 1) * 16;
    const int c0   = cb + lc * 4;
    const int cq0  = c0 >> 2;
    const int p3c0 = (wid >> 1) * 32 + lc * 8;
    const int p3cq = p3c0 >> 2;

    for (int t = 0; t < Tt; ++t) {
        // ===== P2: m = Wh @ h_in (4x4 tiles) =====
        {
            u64 acc[4][2];
            #pragma unroll
            for (int ii = 0; ii < 4; ii++) { acc[ii][0] = acc[ii][1] = 0ULL; }
            #pragma unroll 4
            for (int j = 0; j < 64; j += 4) {
                float4 wr[4]; ulonglong2 hv[4];
                #pragma unroll
                for (int ii = 0; ii < 4; ii++)
                    wr[ii] = *reinterpret_cast<const float4*>(sBuf + a64(r0 + ii, j >> 2));
                #pragma unroll
                for (int jj = 0; jj < 4; jj++)
                    hv[jj] = *reinterpret_cast<const ulonglong2*>(sH + a64(j + jj, cq0));
                #pragma unroll
                for (int ii = 0; ii < 4; ii++) {
                    const float* wf = reinterpret_cast<const float*>(&wr[ii]);
                    #pragma unroll
                    for (int jj = 0; jj < 4; jj++) {
                        u64 wd = dup2(wf[jj]);
                        acc[ii][0] = fma2(wd, hv[jj].x, acc[ii][0]);
                        acc[ii][1] = fma2(wd, hv[jj].y, acc[ii][1]);
                    }
                }
            }
            #pragma unroll
            for (int ii = 0; ii < 4; ii++) {
                ulonglong2 v; v.x = acc[ii][0]; v.y = acc[ii][1];
                *reinterpret_cast<ulonglong2*>(sM + a64(r0 + ii, cq0)) = v;
            }
        }
        __syncthreads();

        // ===== P3: hidden = tanh(m @ w1T + b1), double-buffered weight prefetch =====
        {
            u64 acc[4][4];
            #pragma unroll
            for (int ii = 0; ii < 4; ii++) { acc[ii][0]=acc[ii][1]=acc[ii][2]=acc[ii][3]=0ULL; }
            ulonglong2 wA[2][4], wB[2][4];
            #pragma unroll
            for (int dd = 0; dd < 4; dd++) {
                wA[0][dd] = __ldg(reinterpret_cast<const ulonglong2*>(g_w1T + dd * 128 + p3c0));
                wB[0][dd] = __ldg(reinterpret_cast<const ulonglong2*>(g_w1T + dd * 128 + p3c0 + 4));
            }
            #pragma unroll
            for (int k = 0; k < 16; k++) {
                const int cur = k & 1, nxt = cur ^ 1;
                if (k < 15) {
                    const int d2 = (k + 1) * 4;
                    #pragma unroll
                    for (int dd = 0; dd < 4; dd++) {
                        wA[nxt][dd] = __ldg(reinterpret_cast<const ulonglong2*>(g_w1T + (d2 + dd) * 128 + p3c0));
                        wB[nxt][dd] = __ldg(reinterpret_cast<const ulonglong2*>(g_w1T + (d2 + dd) * 128 + p3c0 + 4));
                    }
                }
                const int d = k * 4;
                float4 mv[4];
                #pragma unroll
                for (int ii = 0; ii < 4; ii++)
                    mv[ii] = *reinterpret_cast<const float4*>(sM + a64(r0 + ii, d >> 2));
                #pragma unroll
                for (int ii = 0; ii < 4; ii++) {
                    const float* mf = reinterpret_cast<const float*>(&mv[ii]);
                    #pragma unroll
                    for (int dd = 0; dd < 4; dd++) {
                        u64 md = dup2(mf[dd]);
                        acc[ii][0] = fma2(md, wA[cur][dd].x, acc[ii][0]);
                        acc[ii][1] = fma2(md, wA[cur][dd].y, acc[ii][1]);
                        acc[ii][2] = fma2(md, wB[cur][dd].x, acc[ii][2]);
                        acc[ii][3] = fma2(md, wB[cur][dd].y, acc[ii][3]);
                    }
                }
            }
            #pragma unroll
            for (int ii = 0; ii < 4; ii++) {
                const int r = r0 + ii;
                float v[8];
                up2(acc[ii][0], v[0], v[1]); up2(acc[ii][1], v[2], v[3]);
                up2(acc[ii][2], v[4], v[5]); up2(acc[ii][3], v[6], v[7]);
                float4 o0, o1;
                o0.x = tfast(v[0] + sB1[p3c0 + 0]); o0.y = tfast(v[1] + sB1[p3c0 + 1]);
                o0.z = tfast(v[2] + sB1[p3c0 + 2]); o0.w = tfast(v[3] + sB1[p3c0 + 3]);
                o1.x = tfast(v[4] + sB1[p3c0 + 4]); o1.y = tfast(v[5] + sB1[p3c0 + 5]);
                o1.z = tfast(v[6] + sB1[p3c0 + 6]); o1.w = tfast(v[7] + sB1[p3c0 + 7]);
                *reinterpret_cast<float4*>(sBuf + a128(r, p3cq))     = o0;
                *reinterpret_cast<float4*>(sBuf + a128(r, p3cq + 1)) = o1;
            }
        }
        __syncthreads();

        // ===== P4: MLP2 + gated update, double-buffered weight prefetch =====
        {
            u64 acc[4][2];
            #pragma unroll
            for (int ii = 0; ii < 4; ii++) { acc[ii][0] = acc[ii][1] = 0ULL; }
            ulonglong2 wv[2][4];
            #pragma unroll
            for (int hh = 0; hh < 4; hh++)
                wv[0][hh] = __ldg(reinterpret_cast<const ulonglong2*>(g_w2T + hh * 64 + c0));
            #pragma unroll
            for (int k = 0; k < 32; k++) {
                const int cur = k & 1, nxt = cur ^ 1;
                if (k < 31) {
                    const int h2 = (k + 1) * 4;
                    #pragma unroll
                    for (int hh = 0; hh < 4; hh++)
                        wv[nxt][hh] = __ldg(reinterpret_cast<const ulonglong2*>(g_w2T + (h2 + hh) * 64 + c0));
                }
                const int h = k * 4;
                float4 tv[4];
                #pragma unroll
                for (int ii = 0; ii < 4; ii++)
                    tv[ii] = *reinterpret_cast<const float4*>(sBuf + a128(r0 + ii, h >> 2));
                #pragma unroll
                for (int ii = 0; ii < 4; ii++) {
                    const float* tf = reinterpret_cast<const float*>(&tv[ii]);
                    #pragma unroll
                    for (int hh = 0; hh < 4; hh++) {
                        u64 td = dup2(tf[hh]);
                        acc[ii][0] = fma2(td, wv[cur][hh].x, acc[ii][0]);
                        acc[ii][1] = fma2(td, wv[cur][hh].y, acc[ii][1]);
                    }
                }
            }
            #pragma unroll
            for (int ii = 0; ii < 4; ii++) {
                const int i = r0 + ii, o = a64(i, cq0);
                const float g = sGam[i], omg = 1.0f - g;
                float4 nv = __ldg(reinterpret_cast<const float4*>(nid + ((long)c * 64 + i) * 64 + c0));
                float v[4];
                up2(acc[ii][0], v[0], v[1]); up2(acc[ii][1], v[2], v[3]);
                float4 hc = *reinterpret_cast<const float4*>(sH + o);
                float4 ov;
                ov.x = omg * hc.x + g * tfast(v[0] + sB2[c0 + 0] + nv.x);
                ov.y = omg * hc.y + g * tfast(v[1] + sB2[c0 + 1] + nv.y);
                ov.z = omg * hc.z + g * tfast(v[2] + sB2[c0 + 2] + nv.z);
                ov.w = omg * hc.w + g * tfast(v[3] + sB2[c0 + 3] + nv.w);
                *reinterpret_cast<float4*>(sH + o) = ov;
            }
        }
        __syncthreads();

        // ===== P5a: readout + gram (reads h_new) + decay update =====
        if (tid < 64) {
            float s = sH[a64s(sOp[0], tid)] + sH[a64s(sOp[1], tid)]
                    + sH[a64s(sOp[2], tid)] + sH[a64s(sOp[3], tid)];
            out[((long)(b * Tt + t) * NCc + c) * 64 + tid] = s * 0.125f;
            sDecW[tid] *= sOmWg[tid];
        }
        u64 acc5[4][4];
        {
            #pragma unroll
            for (int ii = 0; ii < 4; ii++) { acc5[ii][0]=acc5[ii][1]=acc5[ii][2]=acc5[ii][3]=0ULL; }
            #pragma unroll 4
            for (int dq = 0; dq < 64; dq += 4) {
                ulonglong2 hi[4], hj[4];
                #pragma unroll
                for (int ii = 0; ii < 4; ii++)
                    hi[ii] = *reinterpret_cast<const ulonglong2*>(sH + a64(r0 + ii, dq >> 2));
                #pragma unroll
                for (int jj = 0; jj < 4; jj++)
                    hj[jj] = *reinterpret_cast<const ulonglong2*>(sH + a64(c0 + jj, dq >> 2));
                #pragma unroll
                for (int ii = 0; ii < 4; ii++)
                    #pragma unroll
                    for (int jj = 0; jj < 4; jj++) {
                        acc5[ii][jj] = fma2(hi[ii].x, hj[jj].x, acc5[ii][jj]);
                        acc5[ii][jj] = fma2(hi[ii].y, hj[jj].y, acc5[ii][jj]);
                    }
            }
        }
        __syncthreads();

        // ===== P5b: heb store + next Wh build + scatter inj(t+1) =====
        {
            const bool more = (t + 1 < Tt);
            #pragma unroll
            for (int ii = 0; ii < 4; ii++) {
                const int i = r0 + ii, o = a64(i, cq0);
                const float hgv = sHg[i], omh = 1.0f - hgv, sc = hgv * (1.0f / 64.0f);
                float4 e = *reinterpret_cast<const float4*>(sHeb + o);
                float v[4];
                #pragma unroll
                for (int jj = 0; jj < 4; jj++) { float pa, pb; up2(acc5[ii][jj], pa, pb); v[jj] = pa + pb; }
                v[0] = omh * e.x + sc * v[0]; v[1] = omh * e.y + sc * v[1];
                v[2] = omh * e.z + sc * v[2]; v[3] = omh * e.w + sc * v[3];
                #pragma unroll
                for (int jj = 0; jj < 4; jj++) if (i == c0 + jj) v[jj] = 0.0f;
                float4 hn = make_float4(v[0], v[1], v[2], v[3]);
                *reinterpret_cast<float4*>(sHeb + o) = hn;
                if (more) {
                    const float pwn = sDecW[i];
                    float4 w = *reinterpret_cast<const float4*>(sW0 + o);
                    float4 wh;
                    wh.x = fmaf(pwn, w.x, hn.x); wh.y = fmaf(pwn, w.y, hn.y);
                    wh.z = fmaf(pwn, w.z, hn.z); wh.w = fmaf(pwn, w.w, hn.w);
                    *reinterpret_cast<float4*>(sBuf + o) = wh;
                }
            }
            if (more && tid < 64) {
                const long ib = ((long)(b * Tt + t + 1) * NCc + c) * 256 + tid;
                #pragma unroll
                for (int a = 0; a < 4; a++)
                    sH[a64s(sIp[a], tid)] += __ldg(g_inj + ib + a * 64);
            }
        }
        __syncthreads();
    }
}

extern "C" void kernel_launch(void* const* d_in, const int* in_sizes, int n_in,
                              void* d_out, int out_size) {
    const float* x    = (const float*)d_in[0];
    const float* h0   = (const float*)d_in[1];
    const float* W0   = (const float*)d_in[2];
    const float* heb0 = (const float*)d_in[3];
    const float* nid  = (const float*)d_in[4];
    const float* w1   = (const float*)d_in[5];
    const float* b1   = (const float*)d_in[6];
    const float* w2   = (const float*)d_in[7];
    const float* b2   = (const float*)d_in[8];
    const float* injw = (const float*)d_in[9];
    const float* injb = (const float*)d_in[10];
    const float* wdl  = (const float*)d_in[11];
    const float* dgl  = (const float*)d_in[12];
    const float* hdl  = (const float*)d_in[13];
    const int*   ipi  = (const int*)d_in[14];
    const int*   opi  = (const int*)d_in[15];
    float* out = (float*)d_out;

    const int smem_bytes = (4096 * 4 + 8192 + 64 * 4 + 128 + 64) * 4;
    cudaFuncSetAttribute(mg_main, cudaFuncAttributeMaxDynamicSharedMemorySize, smem_bytes);

    mg_prep<<<NCc, 256>>>(x, injw, injb, w1, w2);
    mg_main<<<NCc * Bsz, 256, smem_bytes>>>(h0, W0, heb0, nid, wdl, dgl, hdl,
                                            b1, b2, ipi, opi, out);
}